// round 6
// baseline (speedup 1.0000x reference)
#include <cuda_runtime.h>
#include <math.h>
#include <float.h>

// Problem constants (fixed by the reference setup_inputs)
#define BB 8
#define NN 16384
#define G 64
#define NC (G * G * G)
#define NGRIDS 16                  // (batch, side): side 0 = pred, 1 = target
#define XMIN (-5.0f)
#define CS 0.15625f                // 10/64, exact in binary
#define INV_CS 6.4f
#define CS_SAFE 0.15624f           // strictly-conservative cell size for termination bound
#define BOUND1 (CS_SAFE * CS_SAFE)                 // resolved after 3^3 box if best <= (1*cs)^2
#define BOUND2 (4.0f * CS_SAFE * CS_SAFE)          // resolved after 5^3 box if best <= (2*cs)^2

// Static device scratch (allocation-free, graph-capture safe)
__device__ int    g_count[NGRIDS * NC];          // per-cell counts, reused as scatter cursor
__device__ int    g_start[NGRIDS * (NC + 1)];    // exclusive prefix (cell ranges)
__device__ float4 g_pts[NGRIDS * NN];            // cell-sorted points
__device__ int    g_queue[NGRIDS * NN];          // unresolved query tids
__device__ int    g_qcount;
__device__ double g_acc[2];                      // [0] noise L1 sum, [1] chamfer min-d2 sum

__device__ __forceinline__ int cell_of(float v) {
    int c = (int)floorf((v - XMIN) * INV_CS);
    return min(max(c, 0), G - 1);
}

// ---------------------------------------------------------------------------
__global__ void zero_kernel() {
    const int n = NGRIDS * NC;
    for (int i = blockIdx.x * blockDim.x + threadIdx.x; i < n;
         i += gridDim.x * blockDim.x)
        g_count[i] = 0;
    if (blockIdx.x == 0 && threadIdx.x == 0) {
        g_acc[0] = 0.0; g_acc[1] = 0.0; g_qcount = 0;
    }
}

// ---------------------------------------------------------------------------
__global__ void count_kernel(const float* __restrict__ pred,
                             const float* __restrict__ tgt) {
    int tid = blockIdx.x * blockDim.x + threadIdx.x;
    if (tid >= NGRIDS * NN) return;
    int g = tid >> 14, i = tid & (NN - 1);
    int batch = g >> 1, side = g & 1;
    const float* p = (side ? tgt : pred) + (size_t)(batch * NN + i) * 3;
    int c = (cell_of(p[2]) * G + cell_of(p[1])) * G + cell_of(p[0]);
    atomicAdd(&g_count[g * NC + c], 1);
}

// ---------------------------------------------------------------------------
// One block per grid: 1024 threads, 256 cells each. Produces exclusive prefix
// in g_start and re-zeroes g_count (so it can serve as the scatter cursor).
__global__ void scan_kernel() {
    __shared__ int sh[1024];
    int g = blockIdx.x;
    int t = threadIdx.x;
    int* cnt = g_count + g * NC;
    int* st  = g_start + g * (NC + 1);
    int base = t * 256;

    int sum = 0;
#pragma unroll 8
    for (int i = 0; i < 256; i++) sum += cnt[base + i];
    sh[t] = sum;
    __syncthreads();
    for (int off = 1; off < 1024; off <<= 1) {
        int v = (t >= off) ? sh[t - off] : 0;
        __syncthreads();
        sh[t] += v;
        __syncthreads();
    }
    int run = sh[t] - sum;  // exclusive prefix for this thread's chunk
    for (int i = 0; i < 256; i++) {
        int c = base + i;
        int v = cnt[c];
        st[c] = run;
        run += v;
        cnt[c] = 0;
    }
    if (t == 1023) st[NC] = run;  // == NN
}

// ---------------------------------------------------------------------------
__global__ void scatter_kernel(const float* __restrict__ pred,
                               const float* __restrict__ tgt) {
    int tid = blockIdx.x * blockDim.x + threadIdx.x;
    if (tid >= NGRIDS * NN) return;
    int g = tid >> 14, i = tid & (NN - 1);
    int batch = g >> 1, side = g & 1;
    const float* p = (side ? tgt : pred) + (size_t)(batch * NN + i) * 3;
    float x = p[0], y = p[1], z = p[2];
    int c = (cell_of(z) * G + cell_of(y)) * G + cell_of(x);
    int idx = g_start[g * (NC + 1) + c] + atomicAdd(&g_count[g * NC + c], 1);
    g_pts[g * NN + idx] = make_float4(x, y, z, 0.0f);
}

// ---------------------------------------------------------------------------
// Scan the full (2R+1)^3 cell box around (cx,cy,cz); x-rows are contiguous
// point ranges in the sorted array -> one [b0,e0) scan per row.
__device__ __forceinline__ void scan_box(const float4 p, int cx, int cy, int cz,
                                         int R, const int* __restrict__ st,
                                         const float4* __restrict__ pts,
                                         float& best) {
    int z0 = max(cz - R, 0), z1 = min(cz + R, G - 1);
    int y0 = max(cy - R, 0), y1 = min(cy + R, G - 1);
    int xl = max(cx - R, 0), xh = min(cx + R, G - 1);
    for (int z = z0; z <= z1; z++) {
        int zb = z * (G * G);
        for (int y = y0; y <= y1; y++) {
            int cb = zb + y * G;
            int b0 = st[cb + xl];
            int e0 = st[cb + xh + 1];
            for (int k = b0; k < e0; k++) {
                float4 q = pts[k];
                float dx = p.x - q.x, dy = p.y - q.y, dz = p.z - q.z;
                best = fminf(best, fmaf(dx, dx, fmaf(dy, dy, dz * dz)));
            }
        }
    }
}

// ---------------------------------------------------------------------------
// Pass 1: bounded search. 3^3 box resolves ~93%, 5^3 resolves ~99.2%.
// Leftovers go to a queue for warp-cooperative brute force (pass 2).
__global__ void query_kernel() {
    int tid = blockIdx.x * blockDim.x + threadIdx.x;
    float best = 0.0f;  // contribution to the sum (0 if queued / out of range)

    if (tid < NGRIDS * NN) {
        int qg = tid >> 14, i = tid & (NN - 1);
        int batch = qg >> 1, side = qg & 1;
        int tg = batch * 2 + (1 - side);  // opposite side's grid

        float4 p = g_pts[qg * NN + i];
        const int*    st  = g_start + tg * (NC + 1);
        const float4* pts = g_pts + (size_t)tg * NN;

        int cx = cell_of(p.x), cy = cell_of(p.y), cz = cell_of(p.z);

        float b = FLT_MAX;
        scan_box(p, cx, cy, cz, 1, st, pts, b);
        if (b > BOUND1) {
            scan_box(p, cx, cy, cz, 2, st, pts, b);  // rescan of inner box is harmless
            if (b > BOUND2) {
                int qi = atomicAdd(&g_qcount, 1);
                g_queue[qi] = tid;
                b = 0.0f;  // pass 2 will add the exact min for this query
            }
        }
        best = b;
    }

    // Block-wide sum (256 threads = 8 warps)
    float v = best;
#pragma unroll
    for (int o = 16; o > 0; o >>= 1) v += __shfl_down_sync(0xffffffffu, v, o);
    __shared__ float ws[8];
    int lane = threadIdx.x & 31, w = threadIdx.x >> 5;
    if (lane == 0) ws[w] = v;
    __syncthreads();
    if (w == 0) {
        v = (lane < 8) ? ws[lane] : 0.0f;
#pragma unroll
        for (int o = 4; o > 0; o >>= 1) v += __shfl_down_sync(0xffu, v, o);
        if (lane == 0) atomicAdd(&g_acc[1], (double)v);
    }
}

// ---------------------------------------------------------------------------
// Pass 2: one warp per queued query, brute-force over all NN opposite points.
// Coalesced float4 loads, 4-way unrolled for MLP, warp min-reduce.
__global__ void resolve_kernel() {
    int lane = threadIdx.x & 31;
    int warp_in_block = threadIdx.x >> 5;
    int gwarp = blockIdx.x * (blockDim.x >> 5) + warp_in_block;
    int nwarps = gridDim.x * (blockDim.x >> 5);
    int qn = g_qcount;

    float wsum = 0.0f;
    for (int qi = gwarp; qi < qn; qi += nwarps) {
        int tid = g_queue[qi];
        int qg = tid >> 14, i = tid & (NN - 1);
        int batch = qg >> 1, side = qg & 1;
        int tg = batch * 2 + (1 - side);

        float4 p = g_pts[qg * NN + i];
        const float4* pts = g_pts + (size_t)tg * NN;

        float best = FLT_MAX;
        // NN = 16384; stride 128 per lane => 128 iterations of 4 loads
        for (int k = lane; k < NN; k += 128) {
            float4 q0 = pts[k];
            float4 q1 = pts[k + 32];
            float4 q2 = pts[k + 64];
            float4 q3 = pts[k + 96];
            float dx, dy, dz, d;
            dx = p.x - q0.x; dy = p.y - q0.y; dz = p.z - q0.z;
            d = fmaf(dx, dx, fmaf(dy, dy, dz * dz)); best = fminf(best, d);
            dx = p.x - q1.x; dy = p.y - q1.y; dz = p.z - q1.z;
            d = fmaf(dx, dx, fmaf(dy, dy, dz * dz)); best = fminf(best, d);
            dx = p.x - q2.x; dy = p.y - q2.y; dz = p.z - q2.z;
            d = fmaf(dx, dx, fmaf(dy, dy, dz * dz)); best = fminf(best, d);
            dx = p.x - q3.x; dy = p.y - q3.y; dz = p.z - q3.z;
            d = fmaf(dx, dx, fmaf(dy, dy, dz * dz)); best = fminf(best, d);
        }
#pragma unroll
        for (int o = 16; o > 0; o >>= 1)
            best = fminf(best, __shfl_xor_sync(0xffffffffu, best, o));
        if (lane == 0) wsum += best;
    }

    // Block-level reduction of per-warp sums -> 1 double atomic per block
    __shared__ float ws[8];
    if (lane == 0) ws[warp_in_block] = wsum;
    __syncthreads();
    if (threadIdx.x == 0) {
        float s = 0.0f;
        int nw = blockDim.x >> 5;
        for (int j = 0; j < nw; j++) s += ws[j];
        if (s != 0.0f) atomicAdd(&g_acc[1], (double)s);
    }
}

// ---------------------------------------------------------------------------
__global__ void noise_kernel(const float* __restrict__ a,
                             const float* __restrict__ b, int n) {
    float s = 0.0f;
    for (int i = blockIdx.x * blockDim.x + threadIdx.x; i < n;
         i += gridDim.x * blockDim.x)
        s += fabsf(a[i] - b[i]);
#pragma unroll
    for (int o = 16; o > 0; o >>= 1) s += __shfl_down_sync(0xffffffffu, s, o);
    __shared__ float ws[8];
    int lane = threadIdx.x & 31, w = threadIdx.x >> 5;
    if (lane == 0) ws[w] = s;
    __syncthreads();
    if (w == 0) {
        s = (lane < (blockDim.x >> 5)) ? ws[lane] : 0.0f;
#pragma unroll
        for (int o = 4; o > 0; o >>= 1) s += __shfl_down_sync(0xffu, s, o);
        if (lane == 0) atomicAdd(&g_acc[0], (double)s);
    }
}

// ---------------------------------------------------------------------------
__global__ void finalize_kernel(float* out) {
    double noise   = g_acc[0] / (double)(BB * NN * 3);
    double chamfer = g_acc[1] / (double)(BB * NN);
    out[0] = (float)(noise + 0.1 * chamfer);
}

// ---------------------------------------------------------------------------
extern "C" void kernel_launch(void* const* d_in, const int* in_sizes, int n_in,
                              void* d_out, int out_size) {
    const float* pn = (const float*)d_in[0];  // predicted_noise
    const float* an = (const float*)d_in[1];  // actual_noise
    const float* pp = (const float*)d_in[2];  // predicted_points_coarse
    const float* tp = (const float*)d_in[3];  // target_points_coarse
    float* out = (float*)d_out;

    zero_kernel<<<2048, 1024>>>();
    count_kernel<<<(NGRIDS * NN + 255) / 256, 256>>>(pp, tp);
    scan_kernel<<<NGRIDS, 1024>>>();
    scatter_kernel<<<(NGRIDS * NN + 255) / 256, 256>>>(pp, tp);
    query_kernel<<<(NGRIDS * NN + 255) / 256, 256>>>();
    resolve_kernel<<<128, 256>>>();
    noise_kernel<<<512, 256>>>(pn, an, BB * NN * 3);
    finalize_kernel<<<1, 1>>>(out);
}

// round 7
// speedup vs baseline: 2.0419x; 2.0419x over previous
#include <cuda_runtime.h>
#include <math.h>
#include <float.h>

// Problem constants (fixed by the reference setup_inputs)
#define BB 8
#define NN 16384
#define G 64
#define NC (G * G * G)
#define NCP (NC + 4)               // padded stride for 16B-aligned per-grid slabs
#define NGRIDS 16                  // (batch, side): side 0 = pred, 1 = target
#define XMIN (-5.0f)
#define INV_CS 6.4f
#define CS_SAFE 0.15624f           // strictly-conservative cell size for termination bound
#define BOUND1 (CS_SAFE * CS_SAFE) // resolved after 3^3 box if best <= (1*cs)^2

// Static device scratch (allocation-free, graph-capture safe).
// Invariant: at entry of every kernel_launch call, g_count == 0, g_acc == 0,
// g_qcount == 0. (True at process start via static zero-init; scan re-zeroes
// g_count for the scatter cursor, noise_kernel re-zeroes it after scatter,
// finalize_kernel resets g_acc/g_qcount.)
__device__ __align__(16) int    g_count[NGRIDS * NC];
__device__ __align__(16) int    g_start[NGRIDS * NCP];
__device__ float4 g_pts[NGRIDS * NN];            // cell-sorted points
__device__ int    g_queue[NGRIDS * NN];          // unresolved query tids
__device__ int    g_qcount;
__device__ double g_acc[2];                      // [0] noise L1 sum, [1] chamfer sum

__device__ __forceinline__ int cell_of(float v) {
    int c = (int)floorf((v - XMIN) * INV_CS);
    return min(max(c, 0), G - 1);
}

// ---------------------------------------------------------------------------
__global__ void count_kernel(const float* __restrict__ pred,
                             const float* __restrict__ tgt) {
    int tid = blockIdx.x * blockDim.x + threadIdx.x;
    if (tid >= NGRIDS * NN) return;
    int g = tid >> 14, i = tid & (NN - 1);
    int batch = g >> 1, side = g & 1;
    const float* p = (side ? tgt : pred) + (size_t)(batch * NN + i) * 3;
    int c = (cell_of(p[2]) * G + cell_of(p[1])) * G + cell_of(p[0]);
    atomicAdd(&g_count[g * NC + c], 1);
}

// ---------------------------------------------------------------------------
// One block per grid: 1024 threads x 256 contiguous cells. Exclusive prefix
// into g_start; re-zeroes g_count (scatter cursor). int4-vectorized.
__global__ void scan_kernel() {
    __shared__ int sh[1024];
    int g = blockIdx.x;
    int t = threadIdx.x;
    int* cnt = g_count + g * NC;
    int* st  = g_start + g * NCP;
    int base = t * 256;

    const int4* c4 = (const int4*)(cnt + base);
    int sum = 0;
#pragma unroll 8
    for (int i = 0; i < 64; i++) {
        int4 v = c4[i];
        sum += v.x + v.y + v.z + v.w;
    }
    sh[t] = sum;
    __syncthreads();
    for (int off = 1; off < 1024; off <<= 1) {
        int v = (t >= off) ? sh[t - off] : 0;
        __syncthreads();
        sh[t] += v;
        __syncthreads();
    }
    int run = sh[t] - sum;  // exclusive prefix for this thread's chunk
    int4* st4 = (int4*)(st + base);
    int4* z4  = (int4*)(cnt + base);
#pragma unroll 4
    for (int i = 0; i < 64; i++) {
        int4 v = z4[i];
        int4 o;
        o.x = run; run += v.x;
        o.y = run; run += v.y;
        o.z = run; run += v.z;
        o.w = run; run += v.w;
        st4[i] = o;
        z4[i] = make_int4(0, 0, 0, 0);
    }
    if (t == 1023) st[NC] = run;  // == NN
}

// ---------------------------------------------------------------------------
__global__ void scatter_kernel(const float* __restrict__ pred,
                               const float* __restrict__ tgt) {
    int tid = blockIdx.x * blockDim.x + threadIdx.x;
    if (tid >= NGRIDS * NN) return;
    int g = tid >> 14, i = tid & (NN - 1);
    int batch = g >> 1, side = g & 1;
    const float* p = (side ? tgt : pred) + (size_t)(batch * NN + i) * 3;
    float x = p[0], y = p[1], z = p[2];
    int c = (cell_of(z) * G + cell_of(y)) * G + cell_of(x);
    int idx = g_start[g * NCP + c] + atomicAdd(&g_count[g * NC + c], 1);
    g_pts[g * NN + idx] = make_float4(x, y, z, 0.0f);
}

// ---------------------------------------------------------------------------
// Pass 1: uniform 3^3 box scan, fully unrolled with all 18 row-range loads
// issued up front. Resolves ~90% of queries exactly; the rest are queued
// (warp-aggregated atomic) and contribute 0 here.
__global__ void __launch_bounds__(256) query_kernel() {
    int tid = blockIdx.x * blockDim.x + threadIdx.x;  // always < NGRIDS*NN
    int qg = tid >> 14, i = tid & (NN - 1);
    int batch = qg >> 1, side = qg & 1;
    int tg = batch * 2 + (1 - side);  // opposite side's grid

    float4 p = g_pts[qg * NN + i];
    const int*    st  = g_start + tg * NCP;
    const float4* pts = g_pts + (size_t)tg * NN;

    int cx = cell_of(p.x), cy = cell_of(p.y), cz = cell_of(p.z);
    int x0 = max(cx - 1, 0), x1 = min(cx + 1, G - 1);

    int rb[9], re[9];
#pragma unroll
    for (int j = 0; j < 9; j++) {
        int z = cz + (j / 3) - 1;
        int y = cy + (j % 3) - 1;
        bool ok = ((unsigned)z < G) && ((unsigned)y < G);
        int zc = min(max(z, 0), G - 1);
        int yc = min(max(y, 0), G - 1);
        int cb = (zc * G + yc) * G;
        int b0 = st[cb + x0];
        int e0 = st[cb + x1 + 1];
        rb[j] = b0;
        re[j] = ok ? e0 : b0;
    }

    float b = FLT_MAX;
#pragma unroll
    for (int j = 0; j < 9; j++) {
        for (int k = rb[j]; k < re[j]; k++) {
            float4 q = pts[k];
            float dx = p.x - q.x, dy = p.y - q.y, dz = p.z - q.z;
            b = fminf(b, fmaf(dx, dx, fmaf(dy, dy, dz * dz)));
        }
    }

    bool needq = (b > BOUND1);
    float contrib = needq ? 0.0f : b;

    // Warp-aggregated queue push
    unsigned m = __ballot_sync(0xffffffffu, needq);
    if (m) {
        int lane = threadIdx.x & 31;
        int leader = __ffs(m) - 1;
        int nq = __popc(m);
        int base = 0;
        if (lane == leader) base = atomicAdd(&g_qcount, nq);
        base = __shfl_sync(0xffffffffu, base, leader);
        if (needq)
            g_queue[base + __popc(m & ((1u << lane) - 1u))] = tid;
    }

    // Block-wide sum (256 threads = 8 warps)
    float v = contrib;
#pragma unroll
    for (int o = 16; o > 0; o >>= 1) v += __shfl_down_sync(0xffffffffu, v, o);
    __shared__ float ws[8];
    int lane = threadIdx.x & 31, w = threadIdx.x >> 5;
    if (lane == 0) ws[w] = v;
    __syncthreads();
    if (w == 0) {
        v = (lane < 8) ? ws[lane] : 0.0f;
#pragma unroll
        for (int o = 4; o > 0; o >>= 1) v += __shfl_down_sync(0xffu, v, o);
        if (lane == 0) atomicAdd(&g_acc[1], (double)v);
    }
}

// ---------------------------------------------------------------------------
// Pass 2: one WARP per queued query; exact expanding Chebyshev-shell search
// with the 32 lanes splitting each shell's 24r^2+2 cells. Warp-min per shell,
// terminate when best <= (r*cs)^2 (anything unscanned is farther).
__global__ void resolve_kernel() {
    int lane = threadIdx.x & 31;
    int wib = threadIdx.x >> 5;
    int gwarp = blockIdx.x * (blockDim.x >> 5) + wib;
    int nwarps = gridDim.x * (blockDim.x >> 5);
    int qn = g_qcount;

    float wsum = 0.0f;
    for (int qi = gwarp; qi < qn; qi += nwarps) {
        int tid = g_queue[qi];
        int qg = tid >> 14, i = tid & (NN - 1);
        int batch = qg >> 1, side = qg & 1;
        int tg = batch * 2 + (1 - side);

        float4 p = g_pts[qg * NN + i];
        const int*    st  = g_start + tg * NCP;
        const float4* pts = g_pts + (size_t)tg * NN;
        int cx = cell_of(p.x), cy = cell_of(p.y), cz = cell_of(p.z);

        float best = FLT_MAX;
        for (int r = 0; r < G; r++) {
            int S = (r == 0) ? 1 : (24 * r * r + 2);
            for (int s = lane; s < S; s += 32) {
                int dx, dy, dz;
                if (r == 0) {
                    dx = dy = dz = 0;
                } else {
                    int w2 = 2 * r + 1;
                    int nz = w2 * w2;
                    if (s < 2 * nz) {
                        int f = s / nz, t = s - f * nz;
                        dz = f ? r : -r;
                        dy = t / w2 - r;
                        dx = t - (t / w2) * w2 - r;
                    } else {
                        int s2 = s - 2 * nz;
                        int ny = w2 * (2 * r - 1);
                        if (s2 < 2 * ny) {
                            int f = s2 / ny, t = s2 - f * ny;
                            dy = f ? r : -r;
                            dz = t / w2 - (r - 1);
                            dx = t - (t / w2) * w2 - r;
                        } else {
                            int s3 = s2 - 2 * ny;
                            int w1 = 2 * r - 1;
                            int nx = w1 * w1;
                            int f = s3 / nx, t = s3 - f * nx;
                            dx = f ? r : -r;
                            dz = t / w1 - (r - 1);
                            dy = t - (t / w1) * w1 - (r - 1);
                        }
                    }
                }
                int x = cx + dx, y = cy + dy, z = cz + dz;
                if ((unsigned)x < G && (unsigned)y < G && (unsigned)z < G) {
                    int c = (z * G + y) * G + x;
                    int b0 = st[c], e0 = st[c + 1];
                    for (int k = b0; k < e0; k++) {
                        float4 q = pts[k];
                        float ax = p.x - q.x, ay = p.y - q.y, az = p.z - q.z;
                        best = fminf(best, fmaf(ax, ax, fmaf(ay, ay, az * az)));
                    }
                }
            }
#pragma unroll
            for (int o = 16; o > 0; o >>= 1)
                best = fminf(best, __shfl_xor_sync(0xffffffffu, best, o));
            float bd = (float)r * CS_SAFE;
            if (best <= bd * bd || r == G - 1) break;
        }
        if (lane == 0) wsum += best;
    }

    __shared__ float ws[8];
    if (lane == 0) ws[wib] = wsum;
    __syncthreads();
    if (threadIdx.x == 0) {
        float s = 0.0f;
        int nw = blockDim.x >> 5;
        for (int j = 0; j < nw; j++) s += ws[j];
        if (s != 0.0f) atomicAdd(&g_acc[1], (double)s);
    }
}

// ---------------------------------------------------------------------------
// Noise L1 sum; also re-zeroes g_count (the scatter cursor left it == counts)
// so the next kernel_launch call starts from the required zero state.
__global__ void noise_kernel(const float* __restrict__ a,
                             const float* __restrict__ b, int n) {
    int stride = gridDim.x * blockDim.x;
    for (int i = blockIdx.x * blockDim.x + threadIdx.x; i < NGRIDS * NC / 4;
         i += stride)
        ((int4*)g_count)[i] = make_int4(0, 0, 0, 0);

    float s = 0.0f;
    for (int i = blockIdx.x * blockDim.x + threadIdx.x; i < n; i += stride)
        s += fabsf(a[i] - b[i]);
#pragma unroll
    for (int o = 16; o > 0; o >>= 1) s += __shfl_down_sync(0xffffffffu, s, o);
    __shared__ float ws[8];
    int lane = threadIdx.x & 31, w = threadIdx.x >> 5;
    if (lane == 0) ws[w] = s;
    __syncthreads();
    if (w == 0) {
        s = (lane < (blockDim.x >> 5)) ? ws[lane] : 0.0f;
#pragma unroll
        for (int o = 4; o > 0; o >>= 1) s += __shfl_down_sync(0xffu, s, o);
        if (lane == 0) atomicAdd(&g_acc[0], (double)s);
    }
}

// ---------------------------------------------------------------------------
__global__ void finalize_kernel(float* out) {
    double noise   = g_acc[0] / (double)(BB * NN * 3);
    double chamfer = g_acc[1] / (double)(BB * NN);
    out[0] = (float)(noise + 0.1 * chamfer);
    g_acc[0] = 0.0;   // restore invariant for the next call
    g_acc[1] = 0.0;
    g_qcount = 0;
}

// ---------------------------------------------------------------------------
extern "C" void kernel_launch(void* const* d_in, const int* in_sizes, int n_in,
                              void* d_out, int out_size) {
    const float* pn = (const float*)d_in[0];  // predicted_noise
    const float* an = (const float*)d_in[1];  // actual_noise
    const float* pp = (const float*)d_in[2];  // predicted_points_coarse
    const float* tp = (const float*)d_in[3];  // target_points_coarse
    float* out = (float*)d_out;

    count_kernel<<<(NGRIDS * NN + 255) / 256, 256>>>(pp, tp);
    scan_kernel<<<NGRIDS, 1024>>>();
    scatter_kernel<<<(NGRIDS * NN + 255) / 256, 256>>>(pp, tp);
    query_kernel<<<(NGRIDS * NN) / 256, 256>>>();      // 4th launch -> profiled
    resolve_kernel<<<1024, 256>>>();
    noise_kernel<<<512, 256>>>(pn, an, BB * NN * 3);
    finalize_kernel<<<1, 1>>>(out);
}

// round 9
// speedup vs baseline: 11.0058x; 5.3901x over previous
#include <cuda_runtime.h>
#include <math.h>
#include <float.h>

// Problem constants (fixed by the reference setup_inputs)
#define BB 8
#define NN 16384
#define G 64
#define NC (G * G * G)             // 262144 = 32 * 8192
#define NCP (NC + 4)               // padded per-grid stride for g_start
#define NGRIDS 16                  // (batch, side): side 0 = pred, 1 = target
#define XMIN (-5.0f)
#define INV_CS 6.4f
#define CS_SAFE 0.15624f
#define BOUND1 (CS_SAFE * CS_SAFE)                  // exact after 3^3 box
#define BOUND4 (16.0f * CS_SAFE * CS_SAFE)          // exact after 9^3 box
#define SUBC 8192                  // cells per scan sub-block
#define NSUB 32                    // sub-blocks per grid
#define NBLK (NGRIDS * NSUB)       // 512

// Static device scratch (allocation-free, graph-capture safe).
// Invariant at entry of each kernel_launch: g_count==0, g_acc==0, qcounts==0.
__device__ __align__(16) int    g_count[NGRIDS * NC];
__device__ __align__(16) int    g_start[NGRIDS * NCP];
__device__ float4 g_pts[NGRIDS * NN];
__device__ int    g_queue[NGRIDS * NN];
__device__ int    g_queue2[NGRIDS * NN];
__device__ int    g_qcount, g_qcount2;
__device__ int    g_bsum[NBLK], g_boff[NBLK];
__device__ double g_acc[2];        // [0] noise L1 sum, [1] chamfer sum

__device__ __forceinline__ int cell_of(float v) {
    int c = (int)floorf((v - XMIN) * INV_CS);
    return min(max(c, 0), G - 1);
}

// ---------------------------------------------------------------------------
__global__ void count_kernel(const float* __restrict__ pred,
                             const float* __restrict__ tgt) {
    int tid = blockIdx.x * blockDim.x + threadIdx.x;
    if (tid >= NGRIDS * NN) return;
    int g = tid >> 14, i = tid & (NN - 1);
    int batch = g >> 1, side = g & 1;
    const float* p = (side ? tgt : pred) + (size_t)(batch * NN + i) * 3;
    int c = (cell_of(p[2]) * G + cell_of(p[1])) * G + cell_of(p[0]);
    atomicAdd(&g_count[g * NC + c], 1);
}

// ---------------------------------------------------------------------------
// Scan level 1: 512 blocks, each sums its 8192-cell sub-block (coalesced).
__global__ void scan1_kernel() {
    int t = threadIdx.x;
    const int* cnt = g_count + blockIdx.x * SUBC;  // (g*32+j)*8192 == g*NC+j*8192
    int s = 0;
#pragma unroll
    for (int it = 0; it < SUBC / 256; it++) s += cnt[it * 256 + t];
#pragma unroll
    for (int o = 16; o > 0; o >>= 1) s += __shfl_down_sync(0xffffffffu, s, o);
    __shared__ int ws[8];
    int lane = t & 31, w = t >> 5;
    if (lane == 0) ws[w] = s;
    __syncthreads();
    if (t == 0) {
        int tot = 0;
        for (int k = 0; k < 8; k++) tot += ws[k];
        g_bsum[blockIdx.x] = tot;
    }
}

// Scan level 2: exclusive scan of the 32 sub-block sums within each grid.
__global__ void scan2_kernel() {
    int t = threadIdx.x;  // 512 threads
    int g = t >> 5, j = t & 31;
    int acc = 0;
    for (int k = 0; k < j; k++) acc += g_bsum[g * NSUB + k];
    g_boff[t] = acc;
}

// Scan level 3: per sub-block exclusive scan, coalesced read/write;
// re-zeroes g_count so it can serve as the scatter cursor.
__global__ void scan3_kernel() {
    int t = threadIdx.x, lane = t & 31, w = t >> 5;
    int g = blockIdx.x >> 5, j = blockIdx.x & 31;
    int* cnt = g_count + blockIdx.x * SUBC;
    int* st  = g_start + g * NCP + j * SUBC;
    __shared__ int wsum[8], woff[9];
    int run = g_boff[blockIdx.x];
#pragma unroll 1
    for (int it = 0; it < SUBC / 256; it++) {
        int v = cnt[it * 256 + t];
        cnt[it * 256 + t] = 0;
        int x = v;  // inclusive warp scan
#pragma unroll
        for (int o = 1; o < 32; o <<= 1) {
            int y = __shfl_up_sync(0xffffffffu, x, o);
            if (lane >= o) x += y;
        }
        if (lane == 31) wsum[w] = x;
        __syncthreads();
        if (t < 8) {
            int acc = 0;
            for (int k = 0; k < t; k++) acc += wsum[k];
            woff[t] = acc;
            if (t == 7) woff[8] = acc + wsum[7];
        }
        __syncthreads();
        st[it * 256 + t] = run + woff[w] + (x - v);
        run += woff[8];
        __syncthreads();
    }
    if (j == NSUB - 1 && t == 0) g_start[g * NCP + NC] = run;  // == NN
}

// ---------------------------------------------------------------------------
__global__ void scatter_kernel(const float* __restrict__ pred,
                               const float* __restrict__ tgt) {
    int tid = blockIdx.x * blockDim.x + threadIdx.x;
    if (tid >= NGRIDS * NN) return;
    int g = tid >> 14, i = tid & (NN - 1);
    int batch = g >> 1, side = g & 1;
    const float* p = (side ? tgt : pred) + (size_t)(batch * NN + i) * 3;
    float x = p[0], y = p[1], z = p[2];
    int c = (cell_of(z) * G + cell_of(y)) * G + cell_of(x);
    int idx = g_start[g * NCP + c] + atomicAdd(&g_count[g * NC + c], 1);
    g_pts[g * NN + idx] = make_float4(x, y, z, 0.0f);
}

// ---------------------------------------------------------------------------
// Pass 1: uniform 3^3 box per thread (18 range loads up front). ~90% exact.
__global__ void __launch_bounds__(256) query_kernel() {
    int tid = blockIdx.x * blockDim.x + threadIdx.x;
    int qg = tid >> 14, i = tid & (NN - 1);
    int batch = qg >> 1, side = qg & 1;
    int tg = batch * 2 + (1 - side);

    float4 p = g_pts[qg * NN + i];
    const int*    st  = g_start + tg * NCP;
    const float4* pts = g_pts + (size_t)tg * NN;

    int cx = cell_of(p.x), cy = cell_of(p.y), cz = cell_of(p.z);
    int x0 = max(cx - 1, 0), x1 = min(cx + 1, G - 1);

    int rb[9], re[9];
#pragma unroll
    for (int j = 0; j < 9; j++) {
        int z = cz + (j / 3) - 1;
        int y = cy + (j % 3) - 1;
        bool ok = ((unsigned)z < G) && ((unsigned)y < G);
        int zc = min(max(z, 0), G - 1);
        int yc = min(max(y, 0), G - 1);
        int cb = (zc * G + yc) * G;
        int b0 = st[cb + x0];
        int e0 = st[cb + x1 + 1];
        rb[j] = b0;
        re[j] = ok ? e0 : b0;
    }

    float b = FLT_MAX;
#pragma unroll
    for (int j = 0; j < 9; j++) {
        for (int k = rb[j]; k < re[j]; k++) {
            float4 q = pts[k];
            float dx = p.x - q.x, dy = p.y - q.y, dz = p.z - q.z;
            b = fminf(b, fmaf(dx, dx, fmaf(dy, dy, dz * dz)));
        }
    }

    bool needq = (b > BOUND1);
    float contrib = needq ? 0.0f : b;

    unsigned m = __ballot_sync(0xffffffffu, needq);
    if (m) {
        int lane = threadIdx.x & 31;
        int leader = __ffs(m) - 1;
        int base = 0;
        if (lane == leader) base = atomicAdd(&g_qcount, __popc(m));
        base = __shfl_sync(0xffffffffu, base, leader);
        if (needq)
            g_queue[base + __popc(m & ((1u << lane) - 1u))] = tid;
    }

    float v = contrib;
#pragma unroll
    for (int o = 16; o > 0; o >>= 1) v += __shfl_down_sync(0xffffffffu, v, o);
    __shared__ float ws[8];
    int lane = threadIdx.x & 31, w = threadIdx.x >> 5;
    if (lane == 0) ws[w] = v;
    __syncthreads();
    if (w == 0) {
        v = (lane < 8) ? ws[lane] : 0.0f;
#pragma unroll
        for (int o = 4; o > 0; o >>= 1) v += __shfl_down_sync(0xffu, v, o);
        if (lane == 0) atomicAdd(&g_acc[1], (double)v);
    }
}

// ---------------------------------------------------------------------------
// Pass 2: warp-per-query, uniform 9^3 box as 81 x-rows split over lanes.
// Exact if box-min <= (4*cs)^2; else push to brute-force queue.
__global__ void __launch_bounds__(256) resolve_kernel() {
    int lane = threadIdx.x & 31;
    int wib = threadIdx.x >> 5;
    int gwarp = blockIdx.x * 8 + wib;
    int nwarps = gridDim.x * 8;
    int qn = g_qcount;

    float wsum = 0.0f;
    for (int qi = gwarp; qi < qn; qi += nwarps) {
        int tid = g_queue[qi];
        int qg = tid >> 14, i = tid & (NN - 1);
        int batch = qg >> 1, side = qg & 1;
        int tg = batch * 2 + (1 - side);

        float4 p = g_pts[qg * NN + i];
        const int*    st  = g_start + tg * NCP;
        const float4* pts = g_pts + (size_t)tg * NN;
        int cx = cell_of(p.x), cy = cell_of(p.y), cz = cell_of(p.z);
        int xl = max(cx - 4, 0), xh = min(cx + 4, G - 1);

        float best = FLT_MAX;
#pragma unroll 3
        for (int row = lane; row < 81; row += 32) {
            int z = cz + row / 9 - 4;
            int y = cy + row % 9 - 4;
            if ((unsigned)z < G && (unsigned)y < G) {
                int cb = (z * G + y) * G;
                int b0 = st[cb + xl];
                int e0 = st[cb + xh + 1];
                for (int k = b0; k < e0; k++) {
                    float4 q = pts[k];
                    float ax = p.x - q.x, ay = p.y - q.y, az = p.z - q.z;
                    best = fminf(best, fmaf(ax, ax, fmaf(ay, ay, az * az)));
                }
            }
        }
#pragma unroll
        for (int o = 16; o > 0; o >>= 1)
            best = fminf(best, __shfl_xor_sync(0xffffffffu, best, o));

        if (lane == 0) {
            if (best <= BOUND4) {
                wsum += best;
            } else {
                int q2 = atomicAdd(&g_qcount2, 1);
                g_queue2[q2] = tid;
            }
        }
    }

    __shared__ float ws[8];
    if (lane == 0) ws[wib] = wsum;
    __syncthreads();
    if (threadIdx.x == 0) {
        float s = 0.0f;
        for (int j = 0; j < 8; j++) s += ws[j];
        if (s != 0.0f) atomicAdd(&g_acc[1], (double)s);
    }
}

// ---------------------------------------------------------------------------
// Pass 3: block-per-query (1024 threads) exact brute force over all NN
// opposite points. Coalesced float4 loads, 4-way unrolled, 32-warp reduce.
__global__ void __launch_bounds__(1024) brute_kernel() {
    int t = threadIdx.x, lane = t & 31, w = t >> 5;
    int qn2 = g_qcount2;
    __shared__ float ws[32];
    float bsum = 0.0f;  // accumulated by thread 0

    for (int q = blockIdx.x; q < qn2; q += gridDim.x) {
        int tid = g_queue2[q];
        int qg = tid >> 14, i = tid & (NN - 1);
        int batch = qg >> 1, side = qg & 1;
        int tg = batch * 2 + (1 - side);

        float4 p = g_pts[qg * NN + i];
        const float4* pts = g_pts + (size_t)tg * NN;

        float best = FLT_MAX;
#pragma unroll 1
        for (int k = t; k < NN; k += 4096) {
            float4 q0 = pts[k];
            float4 q1 = pts[k + 1024];
            float4 q2 = pts[k + 2048];
            float4 q3 = pts[k + 3072];
            float dx, dy, dz, d;
            dx = p.x - q0.x; dy = p.y - q0.y; dz = p.z - q0.z;
            d = fmaf(dx, dx, fmaf(dy, dy, dz * dz)); best = fminf(best, d);
            dx = p.x - q1.x; dy = p.y - q1.y; dz = p.z - q1.z;
            d = fmaf(dx, dx, fmaf(dy, dy, dz * dz)); best = fminf(best, d);
            dx = p.x - q2.x; dy = p.y - q2.y; dz = p.z - q2.z;
            d = fmaf(dx, dx, fmaf(dy, dy, dz * dz)); best = fminf(best, d);
            dx = p.x - q3.x; dy = p.y - q3.y; dz = p.z - q3.z;
            d = fmaf(dx, dx, fmaf(dy, dy, dz * dz)); best = fminf(best, d);
        }
#pragma unroll
        for (int o = 16; o > 0; o >>= 1)
            best = fminf(best, __shfl_xor_sync(0xffffffffu, best, o));
        if (lane == 0) ws[w] = best;
        __syncthreads();
        if (t == 0) {
            float bmin = ws[0];
            for (int j = 1; j < 32; j++) bmin = fminf(bmin, ws[j]);
            bsum += bmin;
        }
        __syncthreads();
    }
    if (t == 0 && bsum != 0.0f) atomicAdd(&g_acc[1], (double)bsum);
}

// ---------------------------------------------------------------------------
// Noise L1 sum; also re-zeroes g_count (scatter cursor) for the next call.
__global__ void noise_kernel(const float* __restrict__ a,
                             const float* __restrict__ b, int n) {
    int stride = gridDim.x * blockDim.x;
    for (int i = blockIdx.x * blockDim.x + threadIdx.x; i < NGRIDS * NC / 4;
         i += stride)
        ((int4*)g_count)[i] = make_int4(0, 0, 0, 0);

    float s = 0.0f;
    for (int i = blockIdx.x * blockDim.x + threadIdx.x; i < n; i += stride)
        s += fabsf(a[i] - b[i]);
#pragma unroll
    for (int o = 16; o > 0; o >>= 1) s += __shfl_down_sync(0xffffffffu, s, o);
    __shared__ float ws[8];
    int lane = threadIdx.x & 31, w = threadIdx.x >> 5;
    if (lane == 0) ws[w] = s;
    __syncthreads();
    if (w == 0) {
        s = (lane < (blockDim.x >> 5)) ? ws[lane] : 0.0f;
#pragma unroll
        for (int o = 4; o > 0; o >>= 1) s += __shfl_down_sync(0xffu, s, o);
        if (lane == 0) atomicAdd(&g_acc[0], (double)s);
    }
}

// ---------------------------------------------------------------------------
__global__ void finalize_kernel(float* out) {
    double noise   = g_acc[0] / (double)(BB * NN * 3);
    double chamfer = g_acc[1] / (double)(BB * NN);
    out[0] = (float)(noise + 0.1 * chamfer);
    g_acc[0] = 0.0;   // restore invariants for the next call
    g_acc[1] = 0.0;
    g_qcount = 0;
    g_qcount2 = 0;
}

// ---------------------------------------------------------------------------
extern "C" void kernel_launch(void* const* d_in, const int* in_sizes, int n_in,
                              void* d_out, int out_size) {
    const float* pn = (const float*)d_in[0];
    const float* an = (const float*)d_in[1];
    const float* pp = (const float*)d_in[2];
    const float* tp = (const float*)d_in[3];
    float* out = (float*)d_out;

    count_kernel<<<(NGRIDS * NN + 255) / 256, 256>>>(pp, tp);
    scan1_kernel<<<NBLK, 256>>>();
    scan2_kernel<<<1, NBLK>>>();
    scan3_kernel<<<NBLK, 256>>>();
    scatter_kernel<<<(NGRIDS * NN + 255) / 256, 256>>>(pp, tp);
    query_kernel<<<(NGRIDS * NN) / 256, 256>>>();
    resolve_kernel<<<2048, 256>>>();
    brute_kernel<<<512, 1024>>>();
    noise_kernel<<<512, 256>>>(pn, an, BB * NN * 3);
    finalize_kernel<<<1, 1>>>(out);
}

// round 10
// speedup vs baseline: 11.9052x; 1.0817x over previous
#include <cuda_runtime.h>
#include <math.h>
#include <float.h>

// Problem constants (fixed by the reference setup_inputs)
#define BB 8
#define NN 16384
#define G 64
#define NC (G * G * G)             // 262144 = 32 * 8192
#define NCP (NC + 4)               // padded per-grid stride for g_start
#define NGRIDS 16                  // (batch, side): side 0 = pred, 1 = target
#define XMIN (-5.0f)
#define INV_CS 6.4f
#define CS_SAFE 0.15624f
#define BOUND1 (CS_SAFE * CS_SAFE)                  // exact after 3^3 box
#define BOUND4 (16.0f * CS_SAFE * CS_SAFE)          // exact after 9^3 box
#define SUBC 8192                  // cells per scan sub-block
#define NSUB 32                    // sub-blocks per grid
#define NBLK (NGRIDS * NSUB)       // 512
#define NOISE4 (BB * NN * 3 / 4)   // 98304 float4 elements

// Static device scratch (allocation-free, graph-capture safe).
// Invariant at entry of each kernel_launch: g_count==0, g_acc==0, qcounts==0.
__device__ __align__(16) int    g_count[NGRIDS * NC];
__device__ __align__(16) int    g_start[NGRIDS * NCP];
__device__ float4 g_pts[NGRIDS * NN];
__device__ int    g_queue[NGRIDS * NN];
__device__ int    g_queue2[NGRIDS * NN];
__device__ int    g_qcount, g_qcount2;
__device__ int    g_bsum[NBLK];
__device__ double g_acc[2];        // [0] noise L1 sum, [1] chamfer sum

__device__ __forceinline__ int cell_of(float v) {
    int c = (int)floorf((v - XMIN) * INV_CS);
    return min(max(c, 0), G - 1);
}

// ---------------------------------------------------------------------------
// Fused: per-point cell counting (atomics) + noise L1 partial sum (float4).
__global__ void __launch_bounds__(256) count_noise_kernel(
        const float* __restrict__ pred, const float* __restrict__ tgt,
        const float* __restrict__ pn, const float* __restrict__ an) {
    int tid = blockIdx.x * blockDim.x + threadIdx.x;  // 262144 threads

    // Noise part (vectorized; 98304 float4s over 262144 threads)
    float s = 0.0f;
    if (tid < NOISE4) {
        float4 x = ((const float4*)pn)[tid];
        float4 y = ((const float4*)an)[tid];
        s = fabsf(x.x - y.x) + fabsf(x.y - y.y) +
            fabsf(x.z - y.z) + fabsf(x.w - y.w);
    }
#pragma unroll
    for (int o = 16; o > 0; o >>= 1) s += __shfl_down_sync(0xffffffffu, s, o);
    __shared__ float ws[8];
    int lane = threadIdx.x & 31, w = threadIdx.x >> 5;
    if (lane == 0) ws[w] = s;

    // Count part
    int g = tid >> 14, i = tid & (NN - 1);
    int batch = g >> 1, side = g & 1;
    const float* p = (side ? tgt : pred) + (size_t)(batch * NN + i) * 3;
    int c = (cell_of(p[2]) * G + cell_of(p[1])) * G + cell_of(p[0]);
    atomicAdd(&g_count[g * NC + c], 1);

    __syncthreads();
    if (w == 0) {
        s = (lane < 8) ? ws[lane] : 0.0f;
#pragma unroll
        for (int o = 4; o > 0; o >>= 1) s += __shfl_down_sync(0xffu, s, o);
        if (lane == 0 && s != 0.0f) atomicAdd(&g_acc[0], (double)s);
    }
}

// ---------------------------------------------------------------------------
// Scan level 1: 512 blocks, each sums its 8192-cell sub-block (coalesced).
__global__ void __launch_bounds__(256) scan1_kernel() {
    int t = threadIdx.x;
    const int* cnt = g_count + blockIdx.x * SUBC;
    int s = 0;
#pragma unroll
    for (int it = 0; it < SUBC / 256; it++) s += cnt[it * 256 + t];
#pragma unroll
    for (int o = 16; o > 0; o >>= 1) s += __shfl_down_sync(0xffffffffu, s, o);
    __shared__ int ws[8];
    int lane = t & 31, w = t >> 5;
    if (lane == 0) ws[w] = s;
    __syncthreads();
    if (t == 0) {
        int tot = 0;
        for (int k = 0; k < 8; k++) tot += ws[k];
        g_bsum[blockIdx.x] = tot;
    }
}

// ---------------------------------------------------------------------------
// Scan level 2 (single pass, 1 barrier): each thread owns 32 contiguous
// cells in registers; warp-shuffle scan of 256 thread sums; each block
// derives its own sub-block offset from g_bsum. Re-zeroes g_count.
__global__ void __launch_bounds__(256) scan3_kernel() {
    int t = threadIdx.x, lane = t & 31, w = t >> 5;
    int g = blockIdx.x >> 5, j = blockIdx.x & 31;
    int* cnt = g_count + blockIdx.x * SUBC;
    int* st  = g_start + g * NCP + j * SUBC;

    __shared__ int s_off;
    __shared__ int wsum[8];

    // Sub-block offset within this grid: exclusive scan of g_bsum[g*32..]
    if (w == 0) {
        int v = g_bsum[(blockIdx.x & ~31) + lane];
        int x = v;
#pragma unroll
        for (int o = 1; o < 32; o <<= 1) {
            int y = __shfl_up_sync(0xffffffffu, x, o);
            if (lane >= o) x += y;
        }
        if (lane == j) s_off = x - v;
    }

    // Load this thread's 32 cells, local sum
    int4* c4 = (int4*)(cnt + t * 32);
    int4 v[8];
    int ts = 0;
#pragma unroll
    for (int i = 0; i < 8; i++) {
        v[i] = c4[i];
        ts += v[i].x + v[i].y + v[i].z + v[i].w;
    }
    int xs = ts;  // warp-inclusive scan of thread sums
#pragma unroll
    for (int o = 1; o < 32; o <<= 1) {
        int y = __shfl_up_sync(0xffffffffu, xs, o);
        if (lane >= o) xs += y;
    }
    if (lane == 31) wsum[w] = xs;
    __syncthreads();
    int woff = 0;
#pragma unroll
    for (int k = 0; k < 8; k++) woff += (k < w) ? wsum[k] : 0;

    int run = s_off + woff + (xs - ts);
#pragma unroll
    for (int i = 0; i < 8; i++) {
        int4 o4;
        o4.x = run; run += v[i].x;
        o4.y = run; run += v[i].y;
        o4.z = run; run += v[i].z;
        o4.w = run; run += v[i].w;
        ((int4*)(st + t * 32))[i] = o4;
        c4[i] = make_int4(0, 0, 0, 0);
    }
    if (j == 31 && t == 255) g_start[g * NCP + NC] = run;  // == NN
}

// ---------------------------------------------------------------------------
__global__ void __launch_bounds__(256) scatter_kernel(
        const float* __restrict__ pred, const float* __restrict__ tgt) {
    int tid = blockIdx.x * blockDim.x + threadIdx.x;
    int g = tid >> 14, i = tid & (NN - 1);
    int batch = g >> 1, side = g & 1;
    const float* p = (side ? tgt : pred) + (size_t)(batch * NN + i) * 3;
    float x = p[0], y = p[1], z = p[2];
    int c = (cell_of(z) * G + cell_of(y)) * G + cell_of(x);
    int idx = g_start[g * NCP + c] + atomicAdd(&g_count[g * NC + c], 1);
    g_pts[g * NN + idx] = make_float4(x, y, z, 0.0f);
}

// ---------------------------------------------------------------------------
// Pass 1: uniform 3^3 box per thread (18 range loads up front). ~90% exact.
__global__ void __launch_bounds__(256) query_kernel() {
    int tid = blockIdx.x * blockDim.x + threadIdx.x;
    int qg = tid >> 14, i = tid & (NN - 1);
    int batch = qg >> 1, side = qg & 1;
    int tg = batch * 2 + (1 - side);

    float4 p = g_pts[qg * NN + i];
    const int*    st  = g_start + tg * NCP;
    const float4* pts = g_pts + (size_t)tg * NN;

    int cx = cell_of(p.x), cy = cell_of(p.y), cz = cell_of(p.z);
    int x0 = max(cx - 1, 0), x1 = min(cx + 1, G - 1);

    int rb[9], re[9];
#pragma unroll
    for (int j = 0; j < 9; j++) {
        int z = cz + (j / 3) - 1;
        int y = cy + (j % 3) - 1;
        bool ok = ((unsigned)z < G) && ((unsigned)y < G);
        int zc = min(max(z, 0), G - 1);
        int yc = min(max(y, 0), G - 1);
        int cb = (zc * G + yc) * G;
        int b0 = st[cb + x0];
        int e0 = st[cb + x1 + 1];
        rb[j] = b0;
        re[j] = ok ? e0 : b0;
    }

    float b = FLT_MAX;
#pragma unroll
    for (int j = 0; j < 9; j++) {
        for (int k = rb[j]; k < re[j]; k++) {
            float4 q = pts[k];
            float dx = p.x - q.x, dy = p.y - q.y, dz = p.z - q.z;
            b = fminf(b, fmaf(dx, dx, fmaf(dy, dy, dz * dz)));
        }
    }

    bool needq = (b > BOUND1);
    float contrib = needq ? 0.0f : b;

    unsigned m = __ballot_sync(0xffffffffu, needq);
    if (m) {
        int lane = threadIdx.x & 31;
        int leader = __ffs(m) - 1;
        int base = 0;
        if (lane == leader) base = atomicAdd(&g_qcount, __popc(m));
        base = __shfl_sync(0xffffffffu, base, leader);
        if (needq)
            g_queue[base + __popc(m & ((1u << lane) - 1u))] = tid;
    }

    float v = contrib;
#pragma unroll
    for (int o = 16; o > 0; o >>= 1) v += __shfl_down_sync(0xffffffffu, v, o);
    __shared__ float ws[8];
    int lane = threadIdx.x & 31, w = threadIdx.x >> 5;
    if (lane == 0) ws[w] = v;
    __syncthreads();
    if (w == 0) {
        v = (lane < 8) ? ws[lane] : 0.0f;
#pragma unroll
        for (int o = 4; o > 0; o >>= 1) v += __shfl_down_sync(0xffu, v, o);
        if (lane == 0) atomicAdd(&g_acc[1], (double)v);
    }
}

// ---------------------------------------------------------------------------
// Pass 2: warp-per-query, uniform 9^3 box as 81 x-rows split over lanes.
// Exact if box-min <= (4*cs)^2; else push to brute-force queue.
__global__ void __launch_bounds__(256) resolve_kernel() {
    int lane = threadIdx.x & 31;
    int wib = threadIdx.x >> 5;
    int gwarp = blockIdx.x * 8 + wib;
    int nwarps = gridDim.x * 8;
    int qn = g_qcount;

    float wsum = 0.0f;
    for (int qi = gwarp; qi < qn; qi += nwarps) {
        int tid = g_queue[qi];
        int qg = tid >> 14, i = tid & (NN - 1);
        int batch = qg >> 1, side = qg & 1;
        int tg = batch * 2 + (1 - side);

        float4 p = g_pts[qg * NN + i];
        const int*    st  = g_start + tg * NCP;
        const float4* pts = g_pts + (size_t)tg * NN;
        int cx = cell_of(p.x), cy = cell_of(p.y), cz = cell_of(p.z);
        int xl = max(cx - 4, 0), xh = min(cx + 4, G - 1);

        float best = FLT_MAX;
#pragma unroll 3
        for (int row = lane; row < 81; row += 32) {
            int z = cz + row / 9 - 4;
            int y = cy + row % 9 - 4;
            if ((unsigned)z < G && (unsigned)y < G) {
                int cb = (z * G + y) * G;
                int b0 = st[cb + xl];
                int e0 = st[cb + xh + 1];
                for (int k = b0; k < e0; k++) {
                    float4 q = pts[k];
                    float ax = p.x - q.x, ay = p.y - q.y, az = p.z - q.z;
                    best = fminf(best, fmaf(ax, ax, fmaf(ay, ay, az * az)));
                }
            }
        }
#pragma unroll
        for (int o = 16; o > 0; o >>= 1)
            best = fminf(best, __shfl_xor_sync(0xffffffffu, best, o));

        if (lane == 0) {
            if (best <= BOUND4) {
                wsum += best;
            } else {
                int q2 = atomicAdd(&g_qcount2, 1);
                g_queue2[q2] = tid;
            }
        }
    }

    __shared__ float ws[8];
    if (lane == 0) ws[wib] = wsum;
    __syncthreads();
    if (threadIdx.x == 0) {
        float s = 0.0f;
        for (int j = 0; j < 8; j++) s += ws[j];
        if (s != 0.0f) atomicAdd(&g_acc[1], (double)s);
    }
}

// ---------------------------------------------------------------------------
// Pass 3: block-per-query (1024 threads) exact brute force; also re-zeroes
// g_count (the scatter cursor) so the next kernel_launch starts clean.
__global__ void __launch_bounds__(1024) brute_kernel() {
    int t = threadIdx.x, lane = t & 31, w = t >> 5;

    // Re-zero g_count: 1048576 int4s over 524288 threads (2 each)
    int gt = blockIdx.x * 1024 + t;
    ((int4*)g_count)[gt] = make_int4(0, 0, 0, 0);
    ((int4*)g_count)[gt + 524288] = make_int4(0, 0, 0, 0);

    int qn2 = g_qcount2;
    __shared__ float ws[32];
    float bsum = 0.0f;  // accumulated by thread 0

    for (int q = blockIdx.x; q < qn2; q += gridDim.x) {
        int tid = g_queue2[q];
        int qg = tid >> 14, i = tid & (NN - 1);
        int batch = qg >> 1, side = qg & 1;
        int tg = batch * 2 + (1 - side);

        float4 p = g_pts[qg * NN + i];
        const float4* pts = g_pts + (size_t)tg * NN;

        float best = FLT_MAX;
#pragma unroll 1
        for (int k = t; k < NN; k += 4096) {
            float4 q0 = pts[k];
            float4 q1 = pts[k + 1024];
            float4 q2 = pts[k + 2048];
            float4 q3 = pts[k + 3072];
            float dx, dy, dz, d;
            dx = p.x - q0.x; dy = p.y - q0.y; dz = p.z - q0.z;
            d = fmaf(dx, dx, fmaf(dy, dy, dz * dz)); best = fminf(best, d);
            dx = p.x - q1.x; dy = p.y - q1.y; dz = p.z - q1.z;
            d = fmaf(dx, dx, fmaf(dy, dy, dz * dz)); best = fminf(best, d);
            dx = p.x - q2.x; dy = p.y - q2.y; dz = p.z - q2.z;
            d = fmaf(dx, dx, fmaf(dy, dy, dz * dz)); best = fminf(best, d);
            dx = p.x - q3.x; dy = p.y - q3.y; dz = p.z - q3.z;
            d = fmaf(dx, dx, fmaf(dy, dy, dz * dz)); best = fminf(best, d);
        }
#pragma unroll
        for (int o = 16; o > 0; o >>= 1)
            best = fminf(best, __shfl_xor_sync(0xffffffffu, best, o));
        if (lane == 0) ws[w] = best;
        __syncthreads();
        if (t == 0) {
            float bmin = ws[0];
            for (int j = 1; j < 32; j++) bmin = fminf(bmin, ws[j]);
            bsum += bmin;
        }
        __syncthreads();
    }
    if (t == 0 && bsum != 0.0f) atomicAdd(&g_acc[1], (double)bsum);
}

// ---------------------------------------------------------------------------
__global__ void finalize_kernel(float* out) {
    double noise   = g_acc[0] / (double)(BB * NN * 3);
    double chamfer = g_acc[1] / (double)(BB * NN);
    out[0] = (float)(noise + 0.1 * chamfer);
    g_acc[0] = 0.0;   // restore invariants for the next call
    g_acc[1] = 0.0;
    g_qcount = 0;
    g_qcount2 = 0;
}

// ---------------------------------------------------------------------------
extern "C" void kernel_launch(void* const* d_in, const int* in_sizes, int n_in,
                              void* d_out, int out_size) {
    const float* pn = (const float*)d_in[0];
    const float* an = (const float*)d_in[1];
    const float* pp = (const float*)d_in[2];
    const float* tp = (const float*)d_in[3];
    float* out = (float*)d_out;

    count_noise_kernel<<<(NGRIDS * NN) / 256, 256>>>(pp, tp, pn, an);
    scan1_kernel<<<NBLK, 256>>>();
    scan3_kernel<<<NBLK, 256>>>();
    scatter_kernel<<<(NGRIDS * NN) / 256, 256>>>(pp, tp);
    query_kernel<<<(NGRIDS * NN) / 256, 256>>>();
    resolve_kernel<<<2048, 256>>>();
    brute_kernel<<<512, 1024>>>();
    finalize_kernel<<<1, 1>>>(out);
}